// round 1
// baseline (speedup 1.0000x reference)
#include <cuda_runtime.h>

#define B_SZ 256
#define N_SZ 50
#define D_SZ 128
#define NN   (N_SZ * N_SZ)       // 2500
#define MAX_ATTR 2000
#define NEGV (-9e15f)
#define NTHREADS 512
#define ATTR_BLOCKS 32
#define ATTR_ROWS 8              // batch rows per attr block
#define KSEG (MAX_ATTR / 2)      // 1000 (K split in 2)

struct SessSmem {
    float4 h4[N_SZ * 32];    // [50][32] float4 (h rows)      25600 B
    float  alpha[NN];        // raw e / softmaxed alpha       10000 B
    float4 a4[4 * 32];       // a0..a3 as float4               2048 B
    int    adj[NN];          //                               10000 B
};
struct AttrSmem {
    float4 red[ATTR_ROWS * 32];  // k-split partial reduce     4096 B
};

__global__ __launch_bounds__(NTHREADS)
void session_graph_kernel(const int* __restrict__ inputs,
                          const int* __restrict__ adj,
                          const float* __restrict__ A_attr,
                          const float* __restrict__ emb,
                          const float* __restrict__ attr_emb,
                          const float* __restrict__ a0,
                          const float* __restrict__ a1,
                          const float* __restrict__ a2,
                          const float* __restrict__ a3,
                          float* __restrict__ out)
{
    __shared__ union { SessSmem s; AttrSmem g; } sm;

    const int tid = threadIdx.x;
    const int bb  = blockIdx.x;

    if (bb < B_SZ) {
        // ---------------- Phase 1: stage a-vectors, adj, h into shared ----
        if (tid < 128) {
            int k = tid >> 5, c = tid & 31;
            const float* asrc = (k == 0) ? a0 : (k == 1) ? a1 : (k == 2) ? a2 : a3;
            sm.s.a4[k * 32 + c] = ((const float4*)asrc)[c];
        }
        for (int idx = tid; idx < NN; idx += NTHREADS)
            sm.s.adj[idx] = adj[bb * NN + idx];
        const int* inrow = inputs + bb * N_SZ;
        for (int idx = tid; idx < N_SZ * 32; idx += NTHREADS) {
            int i = idx >> 5, c = idx & 31;
            int node = inrow[i];
            sm.s.h4[idx] = ((const float4*)emb)[node * 32 + c];
        }
        __syncthreads();

        // ---------------- Phase 2: raw attention logits ------------------
        const int warp = tid >> 5;
        const int lane = tid & 31;
        {
            int i = 0, j = warp;
            while (i < N_SZ) {
                int p = i * N_SZ + j;
                int a = sm.s.adj[p];
                if (a == 0) {
                    if (lane == 0) sm.s.alpha[p] = NEGV;
                } else {
                    float4 hi = sm.s.h4[i * 32 + lane];
                    float4 hj = sm.s.h4[j * 32 + lane];
                    float4 av = sm.s.a4[(a - 1) * 32 + lane];
                    float s;
                    // lrelu(x) = max(x,0) + 0.2*min(x,0)
                    float p0 = hi.x * hj.x;
                    float v0 = fmaf(0.2f, fminf(p0, 0.f), fmaxf(p0, 0.f));
                    float p1 = hi.y * hj.y;
                    float v1 = fmaf(0.2f, fminf(p1, 0.f), fmaxf(p1, 0.f));
                    float p2 = hi.z * hj.z;
                    float v2 = fmaf(0.2f, fminf(p2, 0.f), fmaxf(p2, 0.f));
                    float p3 = hi.w * hj.w;
                    float v3 = fmaf(0.2f, fminf(p3, 0.f), fmaxf(p3, 0.f));
                    s = v0 * av.x;
                    s = fmaf(v1, av.y, s);
                    s = fmaf(v2, av.z, s);
                    s = fmaf(v3, av.w, s);
                    #pragma unroll
                    for (int off = 16; off > 0; off >>= 1)
                        s += __shfl_down_sync(0xFFFFFFFFu, s, off);
                    if (lane == 0) sm.s.alpha[p] = s;
                }
                j += 16;
                if (j >= N_SZ) { j -= N_SZ; ++i; }
            }
        }
        __syncthreads();

        // ---------------- Phase 3: row softmax over j ---------------------
        for (int i = warp; i < N_SZ; i += 16) {
            float v0 = sm.s.alpha[i * N_SZ + lane];
            float v1 = (lane < N_SZ - 32) ? sm.s.alpha[i * N_SZ + 32 + lane] : NEGV;
            float m = fmaxf(v0, v1);
            #pragma unroll
            for (int off = 16; off > 0; off >>= 1)
                m = fmaxf(m, __shfl_xor_sync(0xFFFFFFFFu, m, off));
            float e0 = __expf(v0 - m);
            float e1 = (lane < N_SZ - 32) ? __expf(v1 - m) : 0.f;
            float ssum = e0 + e1;
            #pragma unroll
            for (int off = 16; off > 0; off >>= 1)
                ssum += __shfl_xor_sync(0xFFFFFFFFu, ssum, off);
            float inv = 1.0f / ssum;
            sm.s.alpha[i * N_SZ + lane] = e0 * inv;
            if (lane < N_SZ - 32)
                sm.s.alpha[i * N_SZ + 32 + lane] = e1 * inv;
        }
        __syncthreads();

        // ---------------- Phase 4: output = alpha @ h ---------------------
        {
            const int d4 = tid & 31;
            const int ig = tid >> 5;
            for (int i = ig; i < N_SZ; i += 16) {
                float4 acc = make_float4(0.f, 0.f, 0.f, 0.f);
                const float* arow = &sm.s.alpha[i * N_SZ];
                #pragma unroll 5
                for (int j = 0; j < N_SZ; ++j) {
                    float al = arow[j];
                    float4 hv = sm.s.h4[j * 32 + d4];
                    acc.x = fmaf(al, hv.x, acc.x);
                    acc.y = fmaf(al, hv.y, acc.y);
                    acc.z = fmaf(al, hv.z, acc.z);
                    acc.w = fmaf(al, hv.w, acc.w);
                }
                ((float4*)out)[bb * (N_SZ * 32) + i * 32 + d4] = acc;
            }
        }
    } else {
        // ---------------- attr_sess = A_attr @ attr_emb -------------------
        // 32 blocks, 8 batch-rows each, K split in halves across rg groups.
        const int ab  = bb - B_SZ;            // 0..31
        const int r0  = ab * ATTR_ROWS;       // first batch row
        const int d4  = tid & 31;             // float4 column
        const int rg  = tid >> 5;             // 0..15
        const int row = rg & 7;               // 0..7
        const int seg = rg >> 3;              // 0 or 1 (K half)

        const float*  Arow = A_attr + (r0 + row) * MAX_ATTR + seg * KSEG;
        const float4* W    = ((const float4*)attr_emb) + (size_t)seg * KSEG * 32;

        float4 acc = make_float4(0.f, 0.f, 0.f, 0.f);
        #pragma unroll 4
        for (int k = 0; k < KSEG; ++k) {
            float a = Arow[k];
            float4 w = W[k * 32 + d4];
            acc.x = fmaf(a, w.x, acc.x);
            acc.y = fmaf(a, w.y, acc.y);
            acc.z = fmaf(a, w.z, acc.z);
            acc.w = fmaf(a, w.w, acc.w);
        }
        if (seg == 1) sm.g.red[row * 32 + d4] = acc;
        __syncthreads();
        if (seg == 0) {
            float4 o = sm.g.red[row * 32 + d4];
            acc.x += o.x; acc.y += o.y; acc.z += o.z; acc.w += o.w;
            ((float4*)out)[B_SZ * N_SZ * 32 + (r0 + row) * 32 + d4] = acc;
        }
    }
}

extern "C" void kernel_launch(void* const* d_in, const int* in_sizes, int n_in,
                              void* d_out, int out_size)
{
    (void)in_sizes; (void)n_in; (void)out_size;
    const int*   inputs    = (const int*)  d_in[0];
    const int*   adj       = (const int*)  d_in[1];
    // d_in[2] = mask_item (unused by the reference computation)
    const float* A_attr    = (const float*)d_in[3];
    const float* emb       = (const float*)d_in[4];
    const float* attr_emb  = (const float*)d_in[5];
    const float* a0        = (const float*)d_in[6];
    const float* a1        = (const float*)d_in[7];
    const float* a2        = (const float*)d_in[8];
    const float* a3        = (const float*)d_in[9];
    float* out = (float*)d_out;

    session_graph_kernel<<<B_SZ + ATTR_BLOCKS, NTHREADS>>>(
        inputs, adj, A_attr, emb, attr_emb, a0, a1, a2, a3, out);
}

// round 2
// speedup vs baseline: 1.3011x; 1.3011x over previous
#include <cuda_runtime.h>

#define B_SZ 256
#define N_SZ 50
#define NN   (N_SZ * N_SZ)        // 2500
#define MAX_ATTR 2000
#define NEGV (-9e15f)
#define NTHREADS 512
#define ATTR_BLOCKS 64
#define ATTR_ROWS 4               // batch rows per attr block
#define ATTR_SEGS 4
#define KSEG (MAX_ATTR / ATTR_SEGS)   // 500
#define NPAD 33                   // float4 row stride for h (conflict-free both ways)
#define APAD 52                   // float row stride for alpha

struct SessSmem {
    float4 h4p[N_SZ * NPAD];      // 26400 B  (h rows, padded)
    float4 a4p[4 * NPAD];         //  2112 B  (a0..a3, padded)
    float  alpha[N_SZ * APAD];    // 10400 B
    unsigned char adjs[NN + 12];  //  2512 B
};
struct AttrSmem {
    float4 red[(ATTR_SEGS - 1) * ATTR_ROWS * 32];   // 6144 B
};

__global__ __launch_bounds__(NTHREADS, 3)
void session_graph_kernel(const int* __restrict__ inputs,
                          const int* __restrict__ adj,
                          const float* __restrict__ A_attr,
                          const float* __restrict__ emb,
                          const float* __restrict__ attr_emb,
                          const float* __restrict__ a0,
                          const float* __restrict__ a1,
                          const float* __restrict__ a2,
                          const float* __restrict__ a3,
                          float* __restrict__ out)
{
    __shared__ union { SessSmem s; AttrSmem g; } sm;

    const int tid  = threadIdx.x;
    const int bb   = blockIdx.x;
    const int warp = tid >> 5;
    const int lane = tid & 31;

    if (bb < B_SZ) {
        // ------------- Phase 1: stage a, adj (bytes), h into shared -------
        if (tid < 128) {
            int k = tid >> 5, c = tid & 31;
            const float* asrc = (k == 0) ? a0 : (k == 1) ? a1 : (k == 2) ? a2 : a3;
            sm.s.a4p[k * NPAD + c] = ((const float4*)asrc)[c];
        }
        {
            const int* ag = adj + bb * NN;
            for (int idx = tid; idx < NN; idx += NTHREADS)
                sm.s.adjs[idx] = (unsigned char)ag[idx];
        }
        {
            const int* inrow = inputs + bb * N_SZ;
            for (int idx = tid; idx < N_SZ * 32; idx += NTHREADS) {
                int i = idx >> 5, c = idx & 31;
                int node = inrow[i];
                sm.s.h4p[i * NPAD + c] = ((const float4*)emb)[node * 32 + c];
            }
        }
        __syncthreads();

        // ------------- Phase 2+3: logits (no cross-lane reduce) + softmax -
        for (int i = warp; i < N_SZ; i += 16) {
            const float4* hi = &sm.s.h4p[i * NPAD];
            float sres[2];
            #pragma unroll
            for (int half = 0; half < 2; ++half) {
                int j = lane + 32 * half;
                bool act = (j < N_SZ);
                int jj = act ? j : 0;
                int ac = act ? (int)sm.s.adjs[i * N_SZ + jj] : 0;
                const float4* ap = &sm.s.a4p[(ac > 0 ? ac - 1 : 0) * NPAD];
                const float4* hj = &sm.s.h4p[jj * NPAD];
                float4 A = make_float4(0.f, 0.f, 0.f, 0.f);
                #pragma unroll 8
                for (int c = 0; c < 32; ++c) {
                    float4 x  = hi[c];
                    float4 y  = hj[c];
                    float4 av = ap[c];
                    float p, t;
                    p = x.x * y.x; t = fmaf(0.4f, fabsf(p), 0.6f * p); A.x = fmaf(t, av.x, A.x);
                    p = x.y * y.y; t = fmaf(0.4f, fabsf(p), 0.6f * p); A.y = fmaf(t, av.y, A.y);
                    p = x.z * y.z; t = fmaf(0.4f, fabsf(p), 0.6f * p); A.z = fmaf(t, av.z, A.z);
                    p = x.w * y.w; t = fmaf(0.4f, fabsf(p), 0.6f * p); A.w = fmaf(t, av.w, A.w);
                }
                float s = (A.x + A.y) + (A.z + A.w);
                sres[half] = (act && ac != 0) ? s : NEGV;
            }
            // row softmax across 50 entries held in (sres[0] all lanes, sres[1] lanes<18)
            float m = fmaxf(sres[0], sres[1]);
            #pragma unroll
            for (int off = 16; off > 0; off >>= 1)
                m = fmaxf(m, __shfl_xor_sync(0xFFFFFFFFu, m, off));
            float e0 = __expf(sres[0] - m);
            float e1 = (lane < N_SZ - 32) ? __expf(sres[1] - m) : 0.f;
            float ssum = e0 + e1;
            #pragma unroll
            for (int off = 16; off > 0; off >>= 1)
                ssum += __shfl_xor_sync(0xFFFFFFFFu, ssum, off);
            float inv = 1.0f / ssum;
            sm.s.alpha[i * APAD + lane] = e0 * inv;
            if (lane < N_SZ - 32)
                sm.s.alpha[i * APAD + 32 + lane] = e1 * inv;
        }
        __syncthreads();

        // ------------- Phase 4: out = alpha @ h ---------------------------
        for (int i = warp; i < N_SZ; i += 16) {
            float4 acc = make_float4(0.f, 0.f, 0.f, 0.f);
            const float* arow = &sm.s.alpha[i * APAD];
            #pragma unroll 5
            for (int j = 0; j < N_SZ; ++j) {
                float al = arow[j];                  // smem broadcast
                float4 hv = sm.s.h4p[j * NPAD + lane];
                acc.x = fmaf(al, hv.x, acc.x);
                acc.y = fmaf(al, hv.y, acc.y);
                acc.z = fmaf(al, hv.z, acc.z);
                acc.w = fmaf(al, hv.w, acc.w);
            }
            ((float4*)out)[bb * (N_SZ * 32) + i * 32 + lane] = acc;
        }
    } else {
        // ------------- attr_sess = A_attr @ attr_emb ----------------------
        const int ab  = bb - B_SZ;             // 0..63
        const int r0  = ab * ATTR_ROWS;        // first batch row
        const int d4  = lane;                  // float4 column
        const int row = warp & (ATTR_ROWS - 1);
        const int seg = warp >> 2;             // 0..3 (K quarter)

        const float*  Arow = A_attr + (r0 + row) * MAX_ATTR + seg * KSEG;
        const float4* W    = ((const float4*)attr_emb) + (size_t)seg * KSEG * 32;

        float4 acc = make_float4(0.f, 0.f, 0.f, 0.f);
        #pragma unroll 4
        for (int k = 0; k < KSEG; ++k) {
            float a = Arow[k];
            float4 w = W[k * 32 + d4];
            acc.x = fmaf(a, w.x, acc.x);
            acc.y = fmaf(a, w.y, acc.y);
            acc.z = fmaf(a, w.z, acc.z);
            acc.w = fmaf(a, w.w, acc.w);
        }
        if (seg > 0) sm.g.red[((seg - 1) * ATTR_ROWS + row) * 32 + d4] = acc;
        __syncthreads();
        if (seg == 0) {
            #pragma unroll
            for (int s2 = 0; s2 < ATTR_SEGS - 1; ++s2) {
                float4 o = sm.g.red[(s2 * ATTR_ROWS + row) * 32 + d4];
                acc.x += o.x; acc.y += o.y; acc.z += o.z; acc.w += o.w;
            }
            ((float4*)out)[B_SZ * N_SZ * 32 + (r0 + row) * 32 + d4] = acc;
        }
    }
}

extern "C" void kernel_launch(void* const* d_in, const int* in_sizes, int n_in,
                              void* d_out, int out_size)
{
    (void)in_sizes; (void)n_in; (void)out_size;
    const int*   inputs    = (const int*)  d_in[0];
    const int*   adj       = (const int*)  d_in[1];
    // d_in[2] = mask_item (unused by the reference computation)
    const float* A_attr    = (const float*)d_in[3];
    const float* emb       = (const float*)d_in[4];
    const float* attr_emb  = (const float*)d_in[5];
    const float* a0        = (const float*)d_in[6];
    const float* a1        = (const float*)d_in[7];
    const float* a2        = (const float*)d_in[8];
    const float* a3        = (const float*)d_in[9];
    float* out = (float*)d_out;

    session_graph_kernel<<<B_SZ + ATTR_BLOCKS, NTHREADS>>>(
        inputs, adj, A_attr, emb, attr_emb, a0, a1, a2, a3, out);
}